// round 8
// baseline (speedup 1.0000x reference)
#include <cuda_runtime.h>
#include <cuda_fp16.h>
#include <cstdint>

#define STATE_DIM 1024
#define NACT      256
#define MTILE     128
#define KC        128
#define NCHUNK    (STATE_DIM / KC)   // 8
#define NSTAGE    2

// per-stage smem: A kb0 16K | A kb1 16K | B kb0 32K | B kb1 32K = 96KB
#define A_KB1       16384
#define B_OFF       32768
#define B_KB1       32768            // relative to B_OFF
#define STAGE_BYTES 98304
#define SMEM_BYTES  (NSTAGE * STAGE_BYTES + 1024)

// Transformed weights, fp16 (256 x 1024)
__device__ __align__(16) __half g_Wh[NACT * STATE_DIM];

// ---------------- helpers ----------------
__device__ __forceinline__ uint32_t smem_u32(const void* p) {
    uint32_t a;
    asm("{ .reg .u64 t; cvta.to.shared.u64 t, %1; cvt.u32.u64 %0, t; }" : "=r"(a) : "l"(p));
    return a;
}

#define STS128(addr, v) asm volatile("st.shared.v4.b32 [%0], {%1,%2,%3,%4};" \
    :: "r"(addr), "r"((v).x), "r"((v).y), "r"((v).z), "r"((v).w) : "memory")

#define CP_ASYNC16(dst, src) asm volatile( \
    "cp.async.cg.shared.global [%0], [%1], 16;" :: "r"(dst), "l"(src) : "memory")
#define CP_COMMIT()  asm volatile("cp.async.commit_group;" ::: "memory")
#define CP_WAIT(n)   asm volatile("cp.async.wait_group %0;" :: "n"(n) : "memory")

__device__ __forceinline__ void ldm4(uint32_t* d, uint32_t addr) {
    asm volatile("ldmatrix.sync.aligned.m8n8.x4.shared.b16 {%0,%1,%2,%3}, [%4];"
        : "=r"(d[0]), "=r"(d[1]), "=r"(d[2]), "=r"(d[3]) : "r"(addr));
}

__device__ __forceinline__ void mma16816(float* c, const uint32_t* a, uint32_t b0, uint32_t b1) {
    asm volatile("mma.sync.aligned.m16n8k16.row.col.f32.f16.f16.f32 "
        "{%0,%1,%2,%3}, {%4,%5,%6,%7}, {%8,%9}, {%0,%1,%2,%3};"
        : "+f"(c[0]), "+f"(c[1]), "+f"(c[2]), "+f"(c[3])
        : "r"(a[0]), "r"(a[1]), "r"(a[2]), "r"(a[3]), "r"(b0), "r"(b1));
}

// fp32 pair -> packed fp16 pair
__device__ __forceinline__ uint32_t pack_h2(float a, float b) {
    __half2 h = __floats2half2_rn(a, b);
    return *reinterpret_cast<uint32_t*>(&h);
}

// ---------------- prep: fold Hamilton transform into W, convert fp16 ----------------
__global__ void prep_kernel(const float* __restrict__ g, const float* __restrict__ W) {
    int a = blockIdx.x;    // action 0..255
    int n = threadIdx.x;   // quaternion group 0..255
    float4 gv = reinterpret_cast<const float4*>(g)[n];
    float qw = tanhf(gv.x), qi = tanhf(gv.y), qj = tanhf(gv.z), qk = tanhf(gv.w);
    float4 Wv = reinterpret_cast<const float4*>(W + (size_t)a * STATE_DIM)[n];
    float W0 = Wv.x, W1 = Wv.y, W2 = Wv.z, W3 = Wv.w;
    // logits = sum_i x_i * W'_i with W'_i = sum_j W_j * L[j][i]
    float o0 =  W0 * qw + W1 * qi + W2 * qj + W3 * qk;
    float o1 = -W0 * qi + W1 * qw + W2 * qk - W3 * qj;
    float o2 = -W0 * qj - W1 * qk + W2 * qw + W3 * qi;
    float o3 = -W0 * qk + W1 * qj - W2 * qi + W3 * qw;
    reinterpret_cast<uint2*>(g_Wh)[a * 256 + n] =
        make_uint2(pack_h2(o0, o1), pack_h2(o2, o3));
}

// ---------------- main GEMM: out[B,256] = x[B,1024] @ W'^T + b ----------------
// 512 threads = 16 warps, warp grid 2(M) x 8(N), warp tile 64x32.
// 8 K-chunks of 128 (stored as 2 sub-blocks of 64), 2-stage cp.async pipeline.
__global__ void __launch_bounds__(512, 1)
gemm_kernel(const float* __restrict__ x, const float* __restrict__ bias,
            float* __restrict__ out, int Btot) {
    extern __shared__ char smem[];
    const int tid  = threadIdx.x;
    const int wid  = tid >> 5;
    const int lane = tid & 31;
    const int wm   = wid >> 3;   // 0..1
    const int wn   = wid & 7;    // 0..7
    const int m0   = blockIdx.x * MTILE;

    const uint32_t sb    = smem_u32(smem);
    const uint32_t tiles = (sb + 1023u) & ~1023u;

    // ---- producer geometry ----
    // A: per kb-block 128 rows x 8 chunks(16B). thread -> row tid>>2, chunks (tid&3), (tid&3)+4
    const int  apr = tid >> 2;
    const int  apq = tid & 3;
    // B: per kb-block 256 rows x 8 chunks. thread -> row tid>>1, 4 chunks at (tid&1)*4+q
    const int  bpr = tid >> 1;
    const int  bpq = (tid & 1) * 4;
    const float4* xf4 = reinterpret_cast<const float4*>(x);
    const uint4*  bwf = reinterpret_cast<const uint4*>(g_Wh);

    const long aRowG = (long)m0 + apr;
    const bool aval  = aRowG < (long)Btot;

    // ---- ldmatrix lane geometry ----
    const int rA = (lane & 7) | (((lane >> 3) & 1) << 3);  // 0..15
    const int kA = lane >> 4;                              // 0..1
    const int rB = (lane & 7) | (((lane >> 4) & 1) << 3);
    const int kB = (lane >> 3) & 1;
    const uint32_t aRowOff = (uint32_t)((wm * 64 + rA) * 128);
    const uint32_t bRowOff = (uint32_t)((wn * 32 + rB) * 128);
    uint32_t aSwz[4], bSwz[4];
    #pragma unroll
    for (int ks = 0; ks < 4; ks++) {
        aSwz[ks] = (uint32_t)((((2 * ks + kA) ^ (rA & 7)) << 4));
        bSwz[ks] = (uint32_t)((((2 * ks + kB) ^ (rB & 7)) << 4));
    }

    float acc[4][4][4];
    #pragma unroll
    for (int m = 0; m < 4; m++)
        #pragma unroll
        for (int n = 0; n < 4; n++)
            #pragma unroll
            for (int q = 0; q < 4; q++) acc[m][n][q] = 0.0f;

    // converted A chunk held across iterations: [kb*2+h] -> 4 uint4 = 16 regs
    uint4 cvt[4];

    // ---- load + convert A(c) into cvt ----
    auto loadA = [&](int c) {
        size_t base = (size_t)aRowG * 256 + (size_t)c * 32;   // float4 units
        #pragma unroll
        for (int kb = 0; kb < 2; kb++)
            #pragma unroll
            for (int h = 0; h < 2; h++) {
                int ch = apq + 4 * h;
                float4 f0 = aval ? xf4[base + kb * 16 + ch * 2 + 0] : make_float4(0.f,0.f,0.f,0.f);
                float4 f1 = aval ? xf4[base + kb * 16 + ch * 2 + 1] : make_float4(0.f,0.f,0.f,0.f);
                cvt[kb * 2 + h] = make_uint4(pack_h2(f0.x, f0.y), pack_h2(f0.z, f0.w),
                                             pack_h2(f1.x, f1.y), pack_h2(f1.z, f1.w));
            }
    };

    // ---- B cp.async issue for chunk c into stage st ----
    auto issueB = [&](int c, uint32_t st) {
        #pragma unroll
        for (int kb = 0; kb < 2; kb++)
            #pragma unroll
            for (int q = 0; q < 4; q++) {
                int ch = bpq + q;
                uint32_t dst = st + B_OFF + (uint32_t)kb * B_KB1
                             + (uint32_t)(bpr * 128) + (uint32_t)(((ch ^ (bpr & 7)) << 4));
                size_t src = (size_t)bpr * 128 + (size_t)c * 16 + kb * 8 + ch;  // uint4 units
                CP_ASYNC16(dst, (const void*)(bwf + src));
            }
        CP_COMMIT();
    };

    // ---- prologue ----
    loadA(0);
    issueB(0, tiles);

    // ---- main loop ----
    #pragma unroll 1
    for (int c = 0; c < NCHUNK; c++) {
        const int s = c & 1;
        const uint32_t As = tiles + (uint32_t)s * STAGE_BYTES;
        const uint32_t Bs = As + B_OFF;

        // STS A(c) from cvt into stage s (stage's last readers retired at prev barrier)
        #pragma unroll
        for (int kb = 0; kb < 2; kb++)
            #pragma unroll
            for (int h = 0; h < 2; h++) {
                int ch = apq + 4 * h;
                uint32_t ad = As + (uint32_t)kb * A_KB1 + (uint32_t)(apr * 128)
                            + (uint32_t)(((ch ^ (apr & 7)) << 4));
                STS128(ad, cvt[kb * 2 + h]);
            }

        // prefetch + convert A(c+1)
        if (c < NCHUNK - 1) loadA(c + 1);

        // B(c) landed; publish A(c) STS
        CP_WAIT(0);
        __syncthreads();

        // stage s^1 free now (compute(c-1) retired): issue B(c+1), overlaps compute(c)
        if (c < NCHUNK - 1)
            issueB(c + 1, tiles + (uint32_t)(s ^ 1) * STAGE_BYTES);

        // ---- compute chunk c: 2 kb-blocks x 4 K16 slices ----
        #pragma unroll
        for (int kb = 0; kb < 2; kb++) {
            const uint32_t Akb = As + (uint32_t)kb * A_KB1;
            const uint32_t Bkb = Bs + (uint32_t)kb * B_KB1;
            #pragma unroll
            for (int ks = 0; ks < 4; ks++) {
                uint32_t ah[4][4], bh[2][4];
                #pragma unroll
                for (int m = 0; m < 4; m++)
                    ldm4(ah[m], Akb + aRowOff + (uint32_t)(m * 2048) + aSwz[ks]);
                #pragma unroll
                for (int p = 0; p < 2; p++)
                    ldm4(bh[p], Bkb + bRowOff + (uint32_t)(p * 2048) + bSwz[ks]);
                #pragma unroll
                for (int m = 0; m < 4; m++)
                    #pragma unroll
                    for (int p = 0; p < 2; p++) {
                        mma16816(acc[m][2 * p],     ah[m], bh[p][0], bh[p][1]);
                        mma16816(acc[m][2 * p + 1], ah[m], bh[p][2], bh[p][3]);
                    }
            }
        }
    }

    // ---- epilogue: direct STG.64 with bias ----
    const int rrow = m0 + wm * 64 + (lane >> 2);
    const int cb   = wn * 32 + (lane & 3) * 2;
    float2 bv[4];
    #pragma unroll
    for (int n = 0; n < 4; n++)
        bv[n] = *reinterpret_cast<const float2*>(bias + cb + n * 8);
    #pragma unroll
    for (int m = 0; m < 4; m++) {
        int r1 = rrow + m * 16;
        int r2 = r1 + 8;
        #pragma unroll
        for (int n = 0; n < 4; n++) {
            int col = cb + n * 8;
            if (r1 < Btot) {
                float2 v = make_float2(acc[m][n][0] + bv[n].x, acc[m][n][1] + bv[n].y);
                *reinterpret_cast<float2*>(out + (size_t)r1 * NACT + col) = v;
            }
            if (r2 < Btot) {
                float2 v = make_float2(acc[m][n][2] + bv[n].x, acc[m][n][3] + bv[n].y);
                *reinterpret_cast<float2*>(out + (size_t)r2 * NACT + col) = v;
            }
        }
    }
}

// ---------------- launch ----------------
extern "C" void kernel_launch(void* const* d_in, const int* in_sizes, int n_in,
                              void* d_out, int out_size) {
    const float* x = (const float*)d_in[0];
    const float* g = (const float*)d_in[1];
    const float* W = (const float*)d_in[2];
    const float* b = (const float*)d_in[3];
    float* out = (float*)d_out;
    int Btot = in_sizes[0] / STATE_DIM;

    prep_kernel<<<NACT, 256>>>(g, W);

    cudaFuncSetAttribute(gemm_kernel, cudaFuncAttributeMaxDynamicSharedMemorySize, SMEM_BYTES);
    int grid = (Btot + MTILE - 1) / MTILE;
    gemm_kernel<<<grid, 512, SMEM_BYTES>>>(x, b, out, Btot);
}